// round 9
// baseline (speedup 1.0000x reference)
#include <cuda_runtime.h>
#include <math.h>

// SO3 projection, reduced from the SVD reference:
//   Rb    = sign(det A) * U_p^T           (U_p = polar factor of A)
//   trans = -sqrt(3) * U_p^T t / ||A||_F  (sign cancels)
// U_p via scaled Newton (4) + unscaled Newton (2); rel_err ~= 2e-7.
//
// R1-R8 evidence: no pipe saturated, duration invariant to instruction
// count / coalescing / occupancy(>=56%) => exposed memory latency +
// wave structure. This round: PERSISTENT grid-stride kernel (grid
// exactly fills the chip, no wave transitions) with a 1-deep software
// pipeline: the next matrix's 3 LDG.128 are issued before computing
// the current one, hiding load latency under ~400 cyc of math.
// Streaming stores (__stcs) keep the input L2-resident.

#define CTAS_PER_SM 5

__global__ void __launch_bounds__(256, CTAS_PER_SM)
so3_project_kernel(const float4* __restrict__ in, float4* __restrict__ out, int n)
{
    const int stride = gridDim.x * blockDim.x;
    int i = blockIdx.x * blockDim.x + threadIdx.x;
    if (i >= n) return;

    // prologue load
    const float4* p = in + 4 * i;
    float4 r0 = p[0], r1 = p[1], r2 = p[2];

    for (;;) {
        // ---- prefetch next matrix (hidden under this iteration's math) ----
        int  inext = i + stride;
        bool vnext = inext < n;
        float4 q0, q1, q2;
        if (vnext) {
            const float4* q = in + 4 * inext;
            q0 = q[0]; q1 = q[1]; q2 = q[2];
        }

        // ---- compute on current matrix ----
        float x00 = r0.x, x01 = r0.y, x02 = r0.z, t0 = r0.w;
        float x10 = r1.x, x11 = r1.y, x12 = r1.z, t1 = r1.w;
        float x20 = r2.x, x21 = r2.y, x22 = r2.z, t2 = r2.w;

        float detA = x00 * (x11 * x22 - x12 * x21)
                   - x01 * (x10 * x22 - x12 * x20)
                   + x02 * (x10 * x21 - x11 * x20);
        float fro2 = x00 * x00 + x01 * x01 + x02 * x02
                   + x10 * x10 + x11 * x11 + x12 * x12
                   + x20 * x20 + x21 * x21 + x22 * x22;
        float s  = (detA < 0.0f) ? -1.0f : 1.0f;
        float ts = -1.7320508075688772f * rsqrtf(fro2);

        // 4 scaled Newton iterations (RCP runs parallel to LG2->EX2 pair)
#pragma unroll
        for (int it = 0; it < 4; ++it) {
            float c00 = x11 * x22 - x12 * x21;
            float c01 = x12 * x20 - x10 * x22;
            float c02 = x10 * x21 - x11 * x20;
            float c10 = x02 * x21 - x01 * x22;
            float c11 = x00 * x22 - x02 * x20;
            float c12 = x01 * x20 - x00 * x21;
            float c20 = x01 * x12 - x02 * x11;
            float c21 = x02 * x10 - x00 * x12;
            float c22 = x00 * x11 - x01 * x10;
            float d   = x00 * c00 + x01 * c01 + x02 * c02;

            float ad  = fmaxf(fabsf(d), 1e-30f);
            float rd  = __fdividef(1.0f, d);
            float l   = __log2f(ad);
            float hz  = 0.5f * exp2f(-0.3333333333f * l);
            float hzi = 0.5f * exp2f( 0.3333333333f * l);
            float izd = hzi * rd;

            x00 = hz * x00 + izd * c00;
            x01 = hz * x01 + izd * c01;
            x02 = hz * x02 + izd * c02;
            x10 = hz * x10 + izd * c10;
            x11 = hz * x11 + izd * c11;
            x12 = hz * x12 + izd * c12;
            x20 = hz * x20 + izd * c20;
            x21 = hz * x21 + izd * c21;
            x22 = hz * x22 + izd * c22;
        }

        // 2 unscaled Newton iterations
#pragma unroll
        for (int it = 0; it < 2; ++it) {
            float c00 = x11 * x22 - x12 * x21;
            float c01 = x12 * x20 - x10 * x22;
            float c02 = x10 * x21 - x11 * x20;
            float c10 = x02 * x21 - x01 * x22;
            float c11 = x00 * x22 - x02 * x20;
            float c12 = x01 * x20 - x00 * x21;
            float c20 = x01 * x12 - x02 * x11;
            float c21 = x02 * x10 - x00 * x12;
            float c22 = x00 * x11 - x01 * x10;
            float d   = x00 * c00 + x01 * c01 + x02 * c02;

            float izd = __fdividef(0.5f, d);

            x00 = 0.5f * x00 + izd * c00;
            x01 = 0.5f * x01 + izd * c01;
            x02 = 0.5f * x02 + izd * c02;
            x10 = 0.5f * x10 + izd * c10;
            x11 = 0.5f * x11 + izd * c11;
            x12 = 0.5f * x12 + izd * c12;
            x20 = 0.5f * x20 + izd * c20;
            x21 = 0.5f * x21 + izd * c21;
            x22 = 0.5f * x22 + izd * c22;
        }

        // Emit: Rb = s * X^T, trans_i = ts * (col_i(X) . t), row3 = e3
        float tr0 = ts * (x00 * t0 + x10 * t1 + x20 * t2);
        float tr1 = ts * (x01 * t0 + x11 * t1 + x21 * t2);
        float tr2 = ts * (x02 * t0 + x12 * t1 + x22 * t2);

        float4* o = out + 4 * i;
        __stcs(o + 0, make_float4(s * x00, s * x10, s * x20, tr0));
        __stcs(o + 1, make_float4(s * x01, s * x11, s * x21, tr1));
        __stcs(o + 2, make_float4(s * x02, s * x12, s * x22, tr2));
        __stcs(o + 3, make_float4(0.0f, 0.0f, 0.0f, 1.0f));

        if (!vnext) break;
        i  = inext;
        r0 = q0; r1 = q1; r2 = q2;
    }
}

extern "C" void kernel_launch(void* const* d_in, const int* in_sizes, int n_in,
                              void* d_out, int out_size)
{
    const int n = in_sizes[0] / 16;               // number of 4x4 matrices
    const int blocks = 148 * CTAS_PER_SM;         // exactly fill the chip
    so3_project_kernel<<<blocks, 256>>>(
        (const float4*)d_in[0], (float4*)d_out, n);
}

// round 10
// speedup vs baseline: 1.1530x; 1.1530x over previous
#include <cuda_runtime.h>
#include <math.h>

// SO3 projection, reduced from the SVD reference:
//   Rb    = sign(det A) * U_p^T           (U_p = polar factor of A)
//   trans = -sqrt(3) * U_p^T t / ||A||_F  (sign cancels)
// U_p via determinantally-scaled Newton (4 iters) + unscaled Newton
// (2 iters); schedule validated at rel_err ~= 2e-7.
//
// R10 change: kill the per-iteration MUFU chain.
//   zeta = |d|^{-1/3}  via exponent bit-hack (K - i/3) + one Newton
//          refinement (~0.3% error; scaling only needs ~2x accuracy)
//   izd  = 0.5/(zeta*d) = 0.5*sign(d)*zeta^2   -> NO RCP needed
// Scaled iterations now contain ZERO MUFU ops; serial chain per
// iteration drops ~75 -> ~35 cycles. FFMA count unchanged.

__global__ void __launch_bounds__(256, 8)   // 32-reg cap (proven spill-free)
so3_project_kernel(const float4* __restrict__ in, float4* __restrict__ out, int n)
{
    int b = blockIdx.x * blockDim.x + threadIdx.x;
    if (b >= n) return;

    float4 r0 = in[4 * b + 0];
    float4 r1 = in[4 * b + 1];
    float4 r2 = in[4 * b + 2];

    float x00 = r0.x, x01 = r0.y, x02 = r0.z, t0 = r0.w;
    float x10 = r1.x, x11 = r1.y, x12 = r1.z, t1 = r1.w;
    float x20 = r2.x, x21 = r2.y, x22 = r2.z, t2 = r2.w;

    float detA = x00 * (x11 * x22 - x12 * x21)
               - x01 * (x10 * x22 - x12 * x20)
               + x02 * (x10 * x21 - x11 * x20);
    float fro2 = x00 * x00 + x01 * x01 + x02 * x02
               + x10 * x10 + x11 * x11 + x12 * x12
               + x20 * x20 + x21 * x21 + x22 * x22;
    float s  = (detA < 0.0f) ? -1.0f : 1.0f;
    float ts = -1.7320508075688772f * rsqrtf(fro2);

    // ---- 4 scaled Newton iterations:
    //      X <- hz*X + izd*C;  hz = 0.5*zeta, izd = 0.5*sign(d)*zeta^2
#pragma unroll
    for (int it = 0; it < 4; ++it) {
        float c00 = x11 * x22 - x12 * x21;
        float c01 = x12 * x20 - x10 * x22;
        float c02 = x10 * x21 - x11 * x20;
        float c10 = x02 * x21 - x01 * x22;
        float c11 = x00 * x22 - x02 * x20;
        float c12 = x01 * x20 - x00 * x21;
        float c20 = x01 * x12 - x02 * x11;
        float c21 = x02 * x10 - x00 * x12;
        float c22 = x00 * x11 - x01 * x10;
        float d   = x00 * c00 + x01 * c01 + x02 * c02;

        float ad = fmaxf(fabsf(d), 1e-30f);

        // zeta ~= ad^{-1/3}: exponent hack + one Newton step
        // y <- y*(4 - ad*y^3)/3
        float y  = __int_as_float(0x54AAAAAA - __float_as_int(ad) / 3);
        float y2 = y * y;
        float tq = ad * (y2 * y2);                 // ad*y^4
        y = 1.33333333f * y - 0.33333333f * (tq);  // = y*(4/3) - (1/3)ad*y^4

        float hz  = 0.5f * y;
        float izd = copysignf(0.5f * y * y, d);

        x00 = hz * x00 + izd * c00;
        x01 = hz * x01 + izd * c01;
        x02 = hz * x02 + izd * c02;
        x10 = hz * x10 + izd * c10;
        x11 = hz * x11 + izd * c11;
        x12 = hz * x12 + izd * c12;
        x20 = hz * x20 + izd * c20;
        x21 = hz * x21 + izd * c21;
        x22 = hz * x22 + izd * c22;
    }

    // ---- 2 unscaled Newton iterations: X <- 0.5*X + (0.5/d)*C
#pragma unroll
    for (int it = 0; it < 2; ++it) {
        float c00 = x11 * x22 - x12 * x21;
        float c01 = x12 * x20 - x10 * x22;
        float c02 = x10 * x21 - x11 * x20;
        float c10 = x02 * x21 - x01 * x22;
        float c11 = x00 * x22 - x02 * x20;
        float c12 = x01 * x20 - x00 * x21;
        float c20 = x01 * x12 - x02 * x11;
        float c21 = x02 * x10 - x00 * x12;
        float c22 = x00 * x11 - x01 * x10;
        float d   = x00 * c00 + x01 * c01 + x02 * c02;

        float izd = __fdividef(0.5f, d);

        x00 = 0.5f * x00 + izd * c00;
        x01 = 0.5f * x01 + izd * c01;
        x02 = 0.5f * x02 + izd * c02;
        x10 = 0.5f * x10 + izd * c10;
        x11 = 0.5f * x11 + izd * c11;
        x12 = 0.5f * x12 + izd * c12;
        x20 = 0.5f * x20 + izd * c20;
        x21 = 0.5f * x21 + izd * c21;
        x22 = 0.5f * x22 + izd * c22;
    }

    // Emit: Rb = s * X^T, trans_i = ts * (col_i(X) . t), row3 = e3
    float tr0 = ts * (x00 * t0 + x10 * t1 + x20 * t2);
    float tr1 = ts * (x01 * t0 + x11 * t1 + x21 * t2);
    float tr2 = ts * (x02 * t0 + x12 * t1 + x22 * t2);

    out[4 * b + 0] = make_float4(s * x00, s * x10, s * x20, tr0);
    out[4 * b + 1] = make_float4(s * x01, s * x11, s * x21, tr1);
    out[4 * b + 2] = make_float4(s * x02, s * x12, s * x22, tr2);
    out[4 * b + 3] = make_float4(0.0f, 0.0f, 0.0f, 1.0f);
}

extern "C" void kernel_launch(void* const* d_in, const int* in_sizes, int n_in,
                              void* d_out, int out_size)
{
    const int n = in_sizes[0] / 16;
    const int threads = 256;
    const int blocks  = (n + threads - 1) / threads;
    so3_project_kernel<<<blocks, threads>>>(
        (const float4*)d_in[0], (float4*)d_out, n);
}